// round 9
// baseline (speedup 1.0000x reference)
#include <cuda_runtime.h>
#include <math.h>
#include <stdint.h>

#define N_NODES 50000
#define N_EDGES 800000
#define HEADS   8
#define ODIM    8
#define HDIM    64
#define CLAMP_V 5.0f
#define EPS_V   1e-8f
#define TILES   (N_EDGES / 64)      // 12500 tiles of 64 edges
#define EDGE_GRID 296               // 148 SMs * 2 persistent blocks

#define W_STRIDE   68               // sWT row stride in floats (272B, 16B-aligned)
#define EA_STRIDE  68               // sEA row stride (attrs, then scores)
#define KQ_STRIDE  128              // per-edge: K row (64) + Q row (64)
#define SMEM_WT_FLOATS  (128 * W_STRIDE)   // 8704
#define SMEM_EA_FLOATS  (64 * EA_STRIDE)   // 4352 per buffer
#define SMEM_KQ_FLOATS  (64 * KQ_STRIDE)   // 8192
#define SMEM_IDX_FLOATS (2 * 8 * 32)       // 2 buffers x 8 warps x 128B
#define SMEM_EDGE_BYTES ((SMEM_WT_FLOATS + 2 * SMEM_EA_FLOATS + SMEM_KQ_FLOATS + SMEM_IDX_FLOATS) * 4) // 104448

// ---------------- device scratch ----------------
__device__ __align__(16) float g_Qh[N_NODES * HDIM];
__device__ __align__(16) float g_Kh[N_NODES * HDIM];
__device__ __align__(16) float g_Vh[N_NODES * HDIM];
__device__ __align__(16) float g_den[N_NODES * HEADS];
__device__ __align__(16) float g_wV  [N_NODES * HDIM];
__device__ __align__(16) float g_rowV[N_NODES * HDIM];
__device__ unsigned g_orhigh;

// ---------------- helpers ----------------
__device__ __forceinline__ void redAddV4(float* p, float a, float b, float c, float d) {
    asm volatile("red.global.add.v4.f32 [%0], {%1,%2,%3,%4};"
                 :: "l"(p), "f"(a), "f"(b), "f"(c), "f"(d) : "memory");
}
__device__ __forceinline__ void redAdd1(float* p, float v) {
    asm volatile("red.global.add.f32 [%0], %1;" :: "l"(p), "f"(v) : "memory");
}
__device__ __forceinline__ void ffma2(unsigned long long& acc,
                                      unsigned long long a, unsigned long long b) {
    asm("fma.rn.f32x2 %0, %1, %2, %0;" : "+l"(acc) : "l"(a), "l"(b));
}
__device__ __forceinline__ unsigned long long pack2(float lo, float hi) {
    unsigned long long r;
    asm("mov.b64 %0, {%1,%2};" : "=l"(r) : "f"(lo), "f"(hi));
    return r;
}
__device__ __forceinline__ float sum2(unsigned long long v) {
    float2 r;
    asm("mov.b64 {%0,%1}, %2;" : "=f"(r.x), "=f"(r.y) : "l"(v));
    return r.x + r.y;
}
__device__ __forceinline__ float fsqrt_ap(float x) {
    float r; asm("sqrt.approx.f32 %0, %1;" : "=f"(r) : "f"(x)); return r;
}
__device__ __forceinline__ float signed_sqrt(float x) {
    return fsqrt_ap(fmaxf(x, 0.0f) + EPS_V) - fsqrt_ap(fmaxf(-x, 0.0f) + EPS_V);
}
__device__ __forceinline__ void cp_async16(uint32_t smem_addr, const void* gptr) {
    asm volatile("cp.async.cg.shared.global [%0], [%1], 16;"
                 :: "r"(smem_addr), "l"(gptr));
}
__device__ __forceinline__ void cp_commit() {
    asm volatile("cp.async.commit_group;" ::: "memory");
}
__device__ __forceinline__ void cp_wait1() {
    asm volatile("cp.async.wait_group 1;" ::: "memory");
}
__device__ __forceinline__ void cp_wait0() {
    asm volatile("cp.async.wait_group 0;" ::: "memory");
}

// ---------------- kernel 0: init accumulators + dtype flag ----------------
__global__ void k_init() {
    int i = blockIdx.x * blockDim.x + threadIdx.x;
    float4 z = make_float4(0.f, 0.f, 0.f, 0.f);
    if (i < N_NODES * HDIM / 4) {
        reinterpret_cast<float4*>(g_wV)[i] = z;
        reinterpret_cast<float4*>(g_rowV)[i] = z;
    }
    if (i < N_NODES * HEADS / 4) reinterpret_cast<float4*>(g_den)[i] = z;
    if (i == 0) g_orhigh = 0u;
}

// ---------------- kernel 1: index dtype detection ----------------
__global__ void k_detect(const unsigned* __restrict__ raw) {
    int i = blockIdx.x * blockDim.x + threadIdx.x;
    unsigned hi = (i < N_EDGES) ? raw[2 * i + 1] : 0u;
    hi = __reduce_or_sync(0xffffffffu, hi);
    if ((threadIdx.x & 31) == 0 && hi) atomicOr(&g_orhigh, hi);
}

// ---------------- kernel 2: node projections Q,K,V ----------------
__global__ void k_nodeproj(const float* __restrict__ x,
                           const float* __restrict__ Wq, const float* __restrict__ bq,
                           const float* __restrict__ Wk, const float* __restrict__ bk,
                           const float* __restrict__ Wv, const float* __restrict__ bv) {
    __shared__ float sW[64 * 64];
    __shared__ float sA[8][4][64];
    const int tid = threadIdx.x, warp = tid >> 5, lane = tid & 31;
    const int n0 = (blockIdx.x * 8 + warp) * 4;

    #pragma unroll
    for (int n = 0; n < 4; n++) {
        int node = n0 + n; if (node >= N_NODES) node = N_NODES - 1;
        sA[warp][n][lane]      = x[(size_t)node * 64 + lane];
        sA[warp][n][lane + 32] = x[(size_t)node * 64 + lane + 32];
    }

#define PROJ(W, B, OUT) do {                                                  \
    __syncthreads();                                                          \
    for (int i = tid; i < 4096; i += 256) sW[i] = (W)[i];                     \
    __syncthreads();                                                          \
    float b0 = (B)[lane], b1 = (B)[lane + 32];                                \
    float a0c0 = b0, a0c1 = b1, a1c0 = b0, a1c1 = b1;                         \
    float a2c0 = b0, a2c1 = b1, a3c0 = b0, a3c1 = b1;                         \
    _Pragma("unroll 16")                                                      \
    for (int k = 0; k < 64; k++) {                                            \
        float w0 = sW[k * 64 + lane], w1 = sW[k * 64 + lane + 32];            \
        float a0 = sA[warp][0][k], a1 = sA[warp][1][k];                       \
        float a2 = sA[warp][2][k], a3 = sA[warp][3][k];                       \
        a0c0 = fmaf(a0, w0, a0c0); a0c1 = fmaf(a0, w1, a0c1);                 \
        a1c0 = fmaf(a1, w0, a1c0); a1c1 = fmaf(a1, w1, a1c1);                 \
        a2c0 = fmaf(a2, w0, a2c0); a2c1 = fmaf(a2, w1, a2c1);                 \
        a3c0 = fmaf(a3, w0, a3c0); a3c1 = fmaf(a3, w1, a3c1);                 \
    }                                                                         \
    if (n0 + 0 < N_NODES) { (OUT)[(size_t)(n0+0)*64+lane]=a0c0; (OUT)[(size_t)(n0+0)*64+lane+32]=a0c1; } \
    if (n0 + 1 < N_NODES) { (OUT)[(size_t)(n0+1)*64+lane]=a1c0; (OUT)[(size_t)(n0+1)*64+lane+32]=a1c1; } \
    if (n0 + 2 < N_NODES) { (OUT)[(size_t)(n0+2)*64+lane]=a2c0; (OUT)[(size_t)(n0+2)*64+lane+32]=a2c1; } \
    if (n0 + 3 < N_NODES) { (OUT)[(size_t)(n0+3)*64+lane]=a3c0; (OUT)[(size_t)(n0+3)*64+lane+32]=a3c1; } \
} while (0)

    PROJ(Wq, bq, g_Qh);
    PROJ(Wk, bk, g_Kh);
    PROJ(Wv, bv, g_Vh);
#undef PROJ
}

// ---------------- kernel 3: fused edge kernel (software-pipelined) ----------------
// Steady state per tile: attrs+indices for tile t were prefetched during tile
// t-1 (double-buffered, wait_group 0 at loop top = already arrived). KQ gathers
// issued before the GEMM, waited after (covered). All 16B cp.async.
// Commit order per iter: [KQ t] then [attrs+idx t+1]; in-order retirement makes
// wait_group 1 after the GEMM complete exactly KQ[t].
__global__ void __launch_bounds__(256, 2)
k_edge(const float* __restrict__ edge_attr,
       const void* __restrict__ ei_raw,
       const float* __restrict__ We, const float* __restrict__ be,
       const float* __restrict__ Aw,
       float* __restrict__ wE_out) {
    extern __shared__ float smem[];
    float* sWT  = smem;                                  // [128][W_STRIDE]
    float* sEA0 = sWT + SMEM_WT_FLOATS;                  // buffer 0 [64][EA_STRIDE]
    float* sEA1 = sEA0 + SMEM_EA_FLOATS;                 // buffer 1
    float* sKQ  = sEA1 + SMEM_EA_FLOATS;                 // [64][KQ_STRIDE]
    float* sIdx = sKQ + SMEM_KQ_FLOATS;                  // [2][8 warps][128B]
    __shared__ float sP[8][8][8];                        // exp(s) [warp][edge][head]

    const int tid = threadIdx.x, warp = tid >> 5, lane = tid & 31;
    const int e_loc0 = warp * 8;

    // one-time: transpose We into sWT
    for (int i = tid; i < 128 * 64; i += 256) {
        int c = i & 127, k = i >> 7;
        sWT[c * W_STRIDE + k] = We[k * 128 + c];
    }
    __syncthreads();

    const int d0 = lane & 7, h0 = lane >> 3;
    const int cw = (h0 << 4) + d0;
    const float aw0 = Aw[d0 * 8 + h0];
    const float aw1 = Aw[d0 * 8 + h0 + 4];

    const unsigned long long bini0 = pack2(be[cw],      0.f);
    const unsigned long long bini1 = pack2(be[cw + 8],  0.f);
    const unsigned long long bini2 = pack2(be[cw + 64], 0.f);
    const unsigned long long bini3 = pack2(be[cw + 72], 0.f);

    const float* wrow0 = &sWT[(cw)      * W_STRIDE];
    const float* wrow1 = &sWT[(cw + 8)  * W_STRIDE];
    const float* wrow2 = &sWT[(cw + 64) * W_STRIDE];
    const float* wrow3 = &sWT[(cw + 72) * W_STRIDE];

    const bool idx64 = (g_orhigh == 0u);
    const char* raw = (const char*)ei_raw;

    float* eaBuf[2] = { sEA0 + e_loc0 * EA_STRIDE, sEA1 + e_loc0 * EA_STRIDE };
    const uint32_t ea_smem[2] = {
        (uint32_t)__cvta_generic_to_shared(eaBuf[0]),
        (uint32_t)__cvta_generic_to_shared(eaBuf[1]) };
    float* idxBuf[2] = { sIdx + warp * 32, sIdx + 256 + warp * 32 };
    const uint32_t idx_smem[2] = {
        (uint32_t)__cvta_generic_to_shared(idxBuf[0]),
        (uint32_t)__cvta_generic_to_shared(idxBuf[1]) };
    const uint32_t kq_smem = (uint32_t)__cvta_generic_to_shared(
        &sKQ[e_loc0 * KQ_STRIDE]);

    const int l16 = lane & 15, lh = lane >> 4;   // half-warp split

    // issue attrs (4x16B instr) + indices (1x16B instr) for tile T into buffer bb
    auto issue_tile = [&](int T, int bb) {
        int te0 = T * 64 + e_loc0;
        #pragma unroll
        for (int p = 0; p < 4; p++) {
            int eloc = p * 2 + lh;                     // 0..7
            const float* ga = &edge_attr[(size_t)(te0 + eloc) * 64 + l16 * 4];
            cp_async16(ea_smem[bb] + (uint32_t)(eloc * EA_STRIDE + l16 * 4) * 4u, ga);
        }
        if (idx64) {
            if (lane < 8) {
                const char* s = (lane < 4)
                    ? raw + (size_t)te0 * 8 + lane * 16
                    : raw + (size_t)(N_EDGES + te0) * 8 + (lane - 4) * 16;
                cp_async16(idx_smem[bb] + lane * 16u, s);
            }
        } else {
            if (lane < 4) {
                const char* s = (lane < 2)
                    ? raw + (size_t)te0 * 4 + lane * 16
                    : raw + (size_t)(N_EDGES + te0) * 4 + (lane - 2) * 16;
                cp_async16(idx_smem[bb] + lane * 16u, s);
            }
        }
        cp_commit();
    };

    // prologue: prefetch first tile
    int tile = blockIdx.x;
    issue_tile(tile, 0);
    int b = 0;

    for (; tile < TILES; tile += gridDim.x) {
        const int e0 = tile * 64 + e_loc0;
        int ntile = tile + gridDim.x;
        if (ntile >= TILES) ntile = tile;    // harmless dummy prefetch on last iter

        cp_wait0();          // attrs+idx[tile] ready (issued a full tile ago)
        __syncwarp();

        // decode indices from smem
        int srcs[8], dsts[8];
        if (idx64) {
            const long long* q = (const long long*)idxBuf[b];
            #pragma unroll
            for (int n = 0; n < 8; n++) { srcs[n] = (int)q[n]; dsts[n] = (int)q[8 + n]; }
        } else {
            const int* q = (const int*)idxBuf[b];
            #pragma unroll
            for (int n = 0; n < 8; n++) { srcs[n] = q[n]; dsts[n] = q[8 + n]; }
        }

        // issue KQ gathers (group A: covered by GEMM)
        #pragma unroll
        for (int n = 0; n < 8; n++) {
            const float* s = (lh == 0)
                ? &g_Kh[(size_t)srcs[n] * 64 + l16 * 4]
                : &g_Qh[(size_t)dsts[n] * 64 + l16 * 4];
            cp_async16(kq_smem + (uint32_t)(n * KQ_STRIDE + lh * 64 + l16 * 4) * 4u, s);
        }
        cp_commit();

        // issue next tile's attrs+idx (group B: hidden until next iter)
        issue_tile(ntile, b ^ 1);

        // ---- GEMM: 8 edges x 4 cols, FFMA2 (even-k, odd-k) lanes ----
        unsigned long long acc[8][4];
        #pragma unroll
        for (int e = 0; e < 8; e++) {
            acc[e][0] = bini0; acc[e][1] = bini1;
            acc[e][2] = bini2; acc[e][3] = bini3;
        }
        const float* ea = eaBuf[b];
        #pragma unroll 2
        for (int k4 = 0; k4 < 64; k4 += 4) {
            ulonglong2 ww0 = *reinterpret_cast<const ulonglong2*>(wrow0 + k4);
            ulonglong2 ww1 = *reinterpret_cast<const ulonglong2*>(wrow1 + k4);
            ulonglong2 ww2 = *reinterpret_cast<const ulonglong2*>(wrow2 + k4);
            ulonglong2 ww3 = *reinterpret_cast<const ulonglong2*>(wrow3 + k4);
            #pragma unroll
            for (int e = 0; e < 8; e++) {
                ulonglong2 aa = *reinterpret_cast<const ulonglong2*>(
                    &ea[e * EA_STRIDE + k4]);
                ffma2(acc[e][0], aa.x, ww0.x); ffma2(acc[e][0], aa.y, ww0.y);
                ffma2(acc[e][1], aa.x, ww1.x); ffma2(acc[e][1], aa.y, ww1.y);
                ffma2(acc[e][2], aa.x, ww2.x); ffma2(acc[e][2], aa.y, ww2.y);
                ffma2(acc[e][3], aa.x, ww3.x); ffma2(acc[e][3], aa.y, ww3.y);
            }
        }

        cp_wait1();          // KQ[t] done; attrs[t+1] still in flight
        __syncwarp();        // attrs consumed; score stash may overwrite buffer b

        // ---- phase B: scores, wE (stcs), stash, per-head exp, den red ----
        const float* kqb = &sKQ[e_loc0 * KQ_STRIDE];
        float* eaw = eaBuf[b];
        #pragma unroll
        for (int n = 0; n < 8; n++) {
            int e = e0 + n;
            int dst = dsts[n];
            const float* kq = kqb + n * KQ_STRIDE;
            float ew0 = sum2(acc[n][0]);
            float eb0 = sum2(acc[n][1]);
            float ew1 = sum2(acc[n][2]);
            float eb1 = sum2(acc[n][3]);

            float kq0 = kq[lane]      + kq[lane + 64];
            float kq1 = kq[lane + 32] + kq[lane + 96];
            float sc0 = signed_sqrt(kq0 * ew0) + eb0;
            float sc1 = signed_sqrt(kq1 * ew1) + eb1;

            __stcs(&wE_out[(size_t)e * 64 + lane],      sc0);
            __stcs(&wE_out[(size_t)e * 64 + lane + 32], sc1);
            float* srow = eaw + n * EA_STRIDE;
            srow[lane]      = sc0;
            srow[lane + 32] = sc1;

            float p0 = sc0 * aw0;
            float p1 = sc1 * aw1;
            #pragma unroll
            for (int off = 4; off > 0; off >>= 1) {
                p0 += __shfl_xor_sync(0xffffffffu, p0, off);
                p1 += __shfl_xor_sync(0xffffffffu, p1, off);
            }
            p0 = __expf(fminf(fmaxf(p0, -CLAMP_V), CLAMP_V));
            p1 = __expf(fminf(fmaxf(p1, -CLAMP_V), CLAMP_V));
            if (d0 == 0) {
                sP[warp][n][h0]     = p0;
                sP[warp][n][h0 + 4] = p1;
                redAdd1(&g_den[(size_t)dst * 8 + h0],     p0);
                redAdd1(&g_den[(size_t)dst * 8 + h0 + 4], p1);
            }
        }
        __syncwarp();

        // ---- phase C: numerator scatter ----
        // lanes 0-15: exp*V (global gather) -> g_wV; lanes 16-31: exp*e_t (smem) -> g_rowV
        const int q  = lane & 15;
        const int j0 = q * 4;
        const int hq = q >> 1;
        #pragma unroll
        for (int n = 0; n < 8; n++) {
            float p = sP[warp][n][hq];
            int dst = dsts[n];
            if (lane < 16) {
                float4 v = __ldg(reinterpret_cast<const float4*>(
                    &g_Vh[(size_t)srcs[n] * 64 + j0]));
                redAddV4(&g_wV[(size_t)dst * 64 + j0], v.x * p, v.y * p, v.z * p, v.w * p);
            } else {
                float4 et = *reinterpret_cast<const float4*>(&eaw[n * EA_STRIDE + j0]);
                redAddV4(&g_rowV[(size_t)dst * 64 + j0], et.x * p, et.y * p, et.z * p, et.w * p);
            }
        }
        __syncwarp();
        b ^= 1;
    }
}

// ---------------- kernel 4: finalize wV = (wV_raw + rowV_raw @ VeRow) / den ----
__global__ void k_final(const float* __restrict__ VeRow, float* __restrict__ wV_out) {
    int i = blockIdx.x * blockDim.x + threadIdx.x;
    if (i >= N_NODES * HDIM) return;
    int n = i >> 6, j = i & 63;
    int h = j >> 3, c = j & 7;
    float inv = 1.0f / (g_den[(size_t)n * 8 + h] + 1e-16f);
    float acc = g_wV[i];
    const float* rv = &g_rowV[(size_t)n * 64 + h * 8];
    #pragma unroll
    for (int d = 0; d < 8; d++)
        acc = fmaf(rv[d], __ldg(&VeRow[d * 64 + h * 8 + c]), acc);
    wV_out[i] = acc * inv;
}

// ---------------- launch ----------------
extern "C" void kernel_launch(void* const* d_in, const int* in_sizes, int n_in,
                              void* d_out, int out_size) {
    const float* x         = (const float*)d_in[0];
    const float* edge_attr = (const float*)d_in[1];
    const void*  ei_raw    = d_in[2];
    const float* Wq = (const float*)d_in[3];
    const float* bq = (const float*)d_in[4];
    const float* Wk = (const float*)d_in[5];
    const float* bk = (const float*)d_in[6];
    const float* We = (const float*)d_in[7];
    const float* be = (const float*)d_in[8];
    const float* Wv = (const float*)d_in[9];
    const float* bv = (const float*)d_in[10];
    const float* Aw = (const float*)d_in[11];
    const float* VeRow = (const float*)d_in[12];

    float* out    = (float*)d_out;
    float* wV_out = out;
    float* wE_out = out + (size_t)N_NODES * HDIM;

    cudaFuncSetAttribute(k_edge, cudaFuncAttributeMaxDynamicSharedMemorySize,
                         SMEM_EDGE_BYTES);

    k_init<<<(N_NODES * HDIM / 4 + 255) / 256, 256>>>();
    k_detect<<<(N_EDGES + 255) / 256, 256>>>((const unsigned*)ei_raw);
    k_nodeproj<<<(N_NODES + 31) / 32, 256>>>(x, Wq, bq, Wk, bk, Wv, bv);
    k_edge<<<EDGE_GRID, 256, SMEM_EDGE_BYTES>>>(edge_attr, ei_raw, We, be, Aw, wE_out);
    k_final<<<(N_NODES * HDIM + 255) / 256, 256>>>(VeRow, wV_out);
}

// round 10
// speedup vs baseline: 1.2284x; 1.2284x over previous
#include <cuda_runtime.h>
#include <math.h>
#include <stdint.h>

#define N_NODES 50000
#define N_EDGES 800000
#define HEADS   8
#define ODIM    8
#define HDIM    64
#define CLAMP_V 5.0f
#define EPS_V   1e-8f
#define TILES   (N_EDGES / 32)      // 25000 tiles of 32 edges
#define EDGE_GRID 444               // 148 SMs * 3 persistent blocks

#define W_STRIDE   68               // sWT row stride in floats (272B, 16B-aligned)
#define EA_STRIDE  68               // sEA row stride (attrs, then scores)
#define KQV_STRIDE 192              // per-edge: K(64) Q(64) V(64)
#define SMEM_WT_FLOATS  (128 * W_STRIDE)     // 8704
#define SMEM_EA_FLOATS  (32 * EA_STRIDE)     // 2176
#define SMEM_KQV_FLOATS (32 * KQV_STRIDE)    // 6144
#define SMEM_EDGE_BYTES ((SMEM_WT_FLOATS + SMEM_EA_FLOATS + SMEM_KQV_FLOATS) * 4) // 68096

// ---------------- device scratch ----------------
__device__ __align__(16) float g_Qh[N_NODES * HDIM];
__device__ __align__(16) float g_Kh[N_NODES * HDIM];
__device__ __align__(16) float g_Vh[N_NODES * HDIM];
__device__ __align__(16) float g_den[N_NODES * HEADS];
__device__ __align__(16) float g_wV  [N_NODES * HDIM];
__device__ __align__(16) float g_rowV[N_NODES * HDIM];
__device__ unsigned g_orhigh;

// ---------------- helpers ----------------
__device__ __forceinline__ void redAddV4(float* p, float a, float b, float c, float d) {
    asm volatile("red.global.add.v4.f32 [%0], {%1,%2,%3,%4};"
                 :: "l"(p), "f"(a), "f"(b), "f"(c), "f"(d) : "memory");
}
__device__ __forceinline__ void redAdd1(float* p, float v) {
    asm volatile("red.global.add.f32 [%0], %1;" :: "l"(p), "f"(v) : "memory");
}
__device__ __forceinline__ void ffma2(unsigned long long& acc,
                                      unsigned long long a, unsigned long long b) {
    asm("fma.rn.f32x2 %0, %1, %2, %0;" : "+l"(acc) : "l"(a), "l"(b));
}
__device__ __forceinline__ unsigned long long pack2(float lo, float hi) {
    unsigned long long r;
    asm("mov.b64 %0, {%1,%2};" : "=l"(r) : "f"(lo), "f"(hi));
    return r;
}
__device__ __forceinline__ float sum2(unsigned long long v) {
    float2 r;
    asm("mov.b64 {%0,%1}, %2;" : "=f"(r.x), "=f"(r.y) : "l"(v));
    return r.x + r.y;
}
__device__ __forceinline__ float fsqrt_ap(float x) {
    float r; asm("sqrt.approx.f32 %0, %1;" : "=f"(r) : "f"(x)); return r;
}
__device__ __forceinline__ float signed_sqrt(float x) {
    return fsqrt_ap(fmaxf(x, 0.0f) + EPS_V) - fsqrt_ap(fmaxf(-x, 0.0f) + EPS_V);
}
__device__ __forceinline__ void cp_async16(uint32_t smem_addr, const void* gptr) {
    asm volatile("cp.async.cg.shared.global [%0], [%1], 16;"
                 :: "r"(smem_addr), "l"(gptr));
}
__device__ __forceinline__ void cp_commit() {
    asm volatile("cp.async.commit_group;" ::: "memory");
}
__device__ __forceinline__ void cp_wait1() {
    asm volatile("cp.async.wait_group 1;" ::: "memory");
}
__device__ __forceinline__ void cp_wait0() {
    asm volatile("cp.async.wait_group 0;" ::: "memory");
}

// ---------------- kernel 0: init accumulators + dtype flag ----------------
__global__ void k_init() {
    int i = blockIdx.x * blockDim.x + threadIdx.x;
    float4 z = make_float4(0.f, 0.f, 0.f, 0.f);
    if (i < N_NODES * HDIM / 4) {
        reinterpret_cast<float4*>(g_wV)[i] = z;
        reinterpret_cast<float4*>(g_rowV)[i] = z;
    }
    if (i < N_NODES * HEADS / 4) reinterpret_cast<float4*>(g_den)[i] = z;
    if (i == 0) g_orhigh = 0u;
}

// ---------------- kernel 1: index dtype detection ----------------
__global__ void k_detect(const unsigned* __restrict__ raw) {
    int i = blockIdx.x * blockDim.x + threadIdx.x;
    unsigned hi = (i < N_EDGES) ? raw[2 * i + 1] : 0u;
    hi = __reduce_or_sync(0xffffffffu, hi);
    if ((threadIdx.x & 31) == 0 && hi) atomicOr(&g_orhigh, hi);
}

// ---------------- kernel 2: node projections Q,K,V ----------------
__global__ void k_nodeproj(const float* __restrict__ x,
                           const float* __restrict__ Wq, const float* __restrict__ bq,
                           const float* __restrict__ Wk, const float* __restrict__ bk,
                           const float* __restrict__ Wv, const float* __restrict__ bv) {
    __shared__ float sW[64 * 64];
    __shared__ float sA[8][4][64];
    const int tid = threadIdx.x, warp = tid >> 5, lane = tid & 31;
    const int n0 = (blockIdx.x * 8 + warp) * 4;

    #pragma unroll
    for (int n = 0; n < 4; n++) {
        int node = n0 + n; if (node >= N_NODES) node = N_NODES - 1;
        sA[warp][n][lane]      = x[(size_t)node * 64 + lane];
        sA[warp][n][lane + 32] = x[(size_t)node * 64 + lane + 32];
    }

#define PROJ(W, B, OUT) do {                                                  \
    __syncthreads();                                                          \
    for (int i = tid; i < 4096; i += 256) sW[i] = (W)[i];                     \
    __syncthreads();                                                          \
    float b0 = (B)[lane], b1 = (B)[lane + 32];                                \
    float a0c0 = b0, a0c1 = b1, a1c0 = b0, a1c1 = b1;                         \
    float a2c0 = b0, a2c1 = b1, a3c0 = b0, a3c1 = b1;                         \
    _Pragma("unroll 16")                                                      \
    for (int k = 0; k < 64; k++) {                                            \
        float w0 = sW[k * 64 + lane], w1 = sW[k * 64 + lane + 32];            \
        float a0 = sA[warp][0][k], a1 = sA[warp][1][k];                       \
        float a2 = sA[warp][2][k], a3 = sA[warp][3][k];                       \
        a0c0 = fmaf(a0, w0, a0c0); a0c1 = fmaf(a0, w1, a0c1);                 \
        a1c0 = fmaf(a1, w0, a1c0); a1c1 = fmaf(a1, w1, a1c1);                 \
        a2c0 = fmaf(a2, w0, a2c0); a2c1 = fmaf(a2, w1, a2c1);                 \
        a3c0 = fmaf(a3, w0, a3c0); a3c1 = fmaf(a3, w1, a3c1);                 \
    }                                                                         \
    if (n0 + 0 < N_NODES) { (OUT)[(size_t)(n0+0)*64+lane]=a0c0; (OUT)[(size_t)(n0+0)*64+lane+32]=a0c1; } \
    if (n0 + 1 < N_NODES) { (OUT)[(size_t)(n0+1)*64+lane]=a1c0; (OUT)[(size_t)(n0+1)*64+lane+32]=a1c1; } \
    if (n0 + 2 < N_NODES) { (OUT)[(size_t)(n0+2)*64+lane]=a2c0; (OUT)[(size_t)(n0+2)*64+lane+32]=a2c1; } \
    if (n0 + 3 < N_NODES) { (OUT)[(size_t)(n0+3)*64+lane]=a3c0; (OUT)[(size_t)(n0+3)*64+lane+32]=a3c1; } \
} while (0)

    PROJ(Wq, bq, g_Qh);
    PROJ(Wk, bk, g_Kh);
    PROJ(Wv, bv, g_Vh);
#undef PROJ
}

// ---------------- kernel 3: fused edge kernel ----------------
// R7 skeleton (ne=4, occ 3). Per tile: attrs + K/Q/V prefetched via 16B
// cp.async (8 warp instructions total); KQV group waited only AFTER the GEMM
// so its latency hides under ~2000 cycles of FFMA2. Phase C reads V from smem.
__global__ void __launch_bounds__(256, 3)
k_edge(const float* __restrict__ edge_attr,
       const void* __restrict__ ei_raw,
       const float* __restrict__ We, const float* __restrict__ be,
       const float* __restrict__ Aw,
       float* __restrict__ wE_out) {
    extern __shared__ float smem[];
    float* sWT  = smem;                                   // [128][W_STRIDE]
    float* sEA  = smem + SMEM_WT_FLOATS;                  // [32][EA_STRIDE]
    float* sKQV = smem + SMEM_WT_FLOATS + SMEM_EA_FLOATS; // [32][KQV_STRIDE]
    __shared__ float sP[8][4][8];                         // exp(s) [warp][edge][head]

    const int tid = threadIdx.x, warp = tid >> 5, lane = tid & 31;
    const int e_loc0 = warp * 4;

    // one-time: transpose We into sWT
    for (int i = tid; i < 128 * 64; i += 256) {
        int c = i & 127, k = i >> 7;
        sWT[c * W_STRIDE + k] = We[k * 128 + c];
    }
    __syncthreads();

    const int d0 = lane & 7, h0 = lane >> 3;
    const int cw = (h0 << 4) + d0;
    const float aw0 = Aw[d0 * 8 + h0];
    const float aw1 = Aw[d0 * 8 + h0 + 4];

    const unsigned long long bini0 = pack2(be[cw],      0.f);
    const unsigned long long bini1 = pack2(be[cw + 8],  0.f);
    const unsigned long long bini2 = pack2(be[cw + 64], 0.f);
    const unsigned long long bini3 = pack2(be[cw + 72], 0.f);

    const float* wrow0 = &sWT[(cw)      * W_STRIDE];
    const float* wrow1 = &sWT[(cw + 8)  * W_STRIDE];
    const float* wrow2 = &sWT[(cw + 64) * W_STRIDE];
    const float* wrow3 = &sWT[(cw + 72) * W_STRIDE];

    const bool idx64 = (g_orhigh == 0u);
    const long long* p64 = (const long long*)ei_raw;
    const int*       p32 = (const int*)ei_raw;

    const int l16 = lane & 15, lh = lane >> 4;     // half-warp split

    const uint32_t ea_smem = (uint32_t)__cvta_generic_to_shared(
        &sEA[e_loc0 * EA_STRIDE]);
    const uint32_t kqv_smem = (uint32_t)__cvta_generic_to_shared(
        &sKQV[e_loc0 * KQV_STRIDE]);

    for (int tile = blockIdx.x; tile < TILES; tile += gridDim.x) {
        const int e0 = tile * 32 + e_loc0;

        // ---- indices ----
        int srcs[4], dsts[4];
        if (idx64) {
            #pragma unroll
            for (int n = 0; n < 4; n++) {
                srcs[n] = (int)__ldg(&p64[e0 + n]);
                dsts[n] = (int)__ldg(&p64[N_EDGES + e0 + n]);
            }
        } else {
            #pragma unroll
            for (int n = 0; n < 4; n++) {
                srcs[n] = __ldg(&p32[e0 + n]);
                dsts[n] = __ldg(&p32[N_EDGES + e0 + n]);
            }
        }

        // ---- group 0: edge attrs, 2x cp16 (lanes 0-15 -> edge 2m, 16-31 -> 2m+1)
        #pragma unroll
        for (int m = 0; m < 2; m++) {
            const float* ga = &edge_attr[(size_t)(e0 + 2 * m + lh) * 64 + l16 * 4];
            cp_async16(ea_smem + (uint32_t)((2 * m + lh) * EA_STRIDE + l16 * 4) * 4u, ga);
        }
        cp_commit();

        // ---- group 1: K/Q (4x cp16) + V (2x cp16), covered by GEMM ----
        #pragma unroll
        for (int n = 0; n < 4; n++) {
            const float* s = (lh == 0)
                ? &g_Kh[(size_t)srcs[n] * 64 + l16 * 4]
                : &g_Qh[(size_t)dsts[n] * 64 + l16 * 4];
            cp_async16(kqv_smem + (uint32_t)(n * KQV_STRIDE + lh * 64 + l16 * 4) * 4u, s);
        }
        #pragma unroll
        for (int m = 0; m < 2; m++) {
            int sv = (lh == 0) ? srcs[2 * m] : srcs[2 * m + 1];
            const float* s = &g_Vh[(size_t)sv * 64 + l16 * 4];
            cp_async16(kqv_smem + (uint32_t)((2 * m + lh) * KQV_STRIDE + 128 + l16 * 4) * 4u, s);
        }
        cp_commit();

        cp_wait1();          // attrs ready; KQV still in flight
        __syncwarp();

        // ---- GEMM: 4 edges x 4 cols, FFMA2 (even-k, odd-k) lanes ----
        unsigned long long acc[4][4];
        #pragma unroll
        for (int e = 0; e < 4; e++) {
            acc[e][0] = bini0; acc[e][1] = bini1;
            acc[e][2] = bini2; acc[e][3] = bini3;
        }

        #pragma unroll 4
        for (int k4 = 0; k4 < 64; k4 += 4) {
            ulonglong2 ww0 = *reinterpret_cast<const ulonglong2*>(wrow0 + k4);
            ulonglong2 ww1 = *reinterpret_cast<const ulonglong2*>(wrow1 + k4);
            ulonglong2 ww2 = *reinterpret_cast<const ulonglong2*>(wrow2 + k4);
            ulonglong2 ww3 = *reinterpret_cast<const ulonglong2*>(wrow3 + k4);
            #pragma unroll
            for (int e = 0; e < 4; e++) {
                ulonglong2 aa = *reinterpret_cast<const ulonglong2*>(
                    &sEA[(e_loc0 + e) * EA_STRIDE + k4]);
                ffma2(acc[e][0], aa.x, ww0.x); ffma2(acc[e][0], aa.y, ww0.y);
                ffma2(acc[e][1], aa.x, ww1.x); ffma2(acc[e][1], aa.y, ww1.y);
                ffma2(acc[e][2], aa.x, ww2.x); ffma2(acc[e][2], aa.y, ww2.y);
                ffma2(acc[e][3], aa.x, ww3.x); ffma2(acc[e][3], aa.y, ww3.y);
            }
        }

        cp_wait0();          // KQV ready
        __syncwarp();        // attrs consumed; score stash may overwrite

        // ---- phase B: scores (stcs + smem stash), per-head exp, den red ----
        #pragma unroll
        for (int n = 0; n < 4; n++) {
            int e = e0 + n;
            int dst = dsts[n];
            const float* kqv = &sKQV[(e_loc0 + n) * KQV_STRIDE];
            float ew0 = sum2(acc[n][0]);
            float eb0 = sum2(acc[n][1]);
            float ew1 = sum2(acc[n][2]);
            float eb1 = sum2(acc[n][3]);

            float kq0 = kqv[lane]      + kqv[lane + 64];
            float kq1 = kqv[lane + 32] + kqv[lane + 96];
            float sc0 = signed_sqrt(kq0 * ew0) + eb0;
            float sc1 = signed_sqrt(kq1 * ew1) + eb1;

            __stcs(&wE_out[(size_t)e * 64 + lane],      sc0);
            __stcs(&wE_out[(size_t)e * 64 + lane + 32], sc1);
            float* srow = &sEA[(e_loc0 + n) * EA_STRIDE];
            srow[lane]      = sc0;
            srow[lane + 32] = sc1;

            float p0 = sc0 * aw0;
            float p1 = sc1 * aw1;
            #pragma unroll
            for (int off = 4; off > 0; off >>= 1) {
                p0 += __shfl_xor_sync(0xffffffffu, p0, off);
                p1 += __shfl_xor_sync(0xffffffffu, p1, off);
            }
            p0 = __expf(fminf(fmaxf(p0, -CLAMP_V), CLAMP_V));
            p1 = __expf(fminf(fmaxf(p1, -CLAMP_V), CLAMP_V));
            if (d0 == 0) {
                sP[warp][n][h0]     = p0;
                sP[warp][n][h0 + 4] = p1;
                redAdd1(&g_den[(size_t)dst * 8 + h0],     p0);
                redAdd1(&g_den[(size_t)dst * 8 + h0 + 4], p1);
            }
        }
        __syncwarp();

        // ---- phase C: numerator scatter (all operands in smem) ----
        // lanes 0-15: exp*V -> g_wV; lanes 16-31: exp*e_t -> g_rowV
        const int q  = lane & 15;
        const int j0 = q * 4;
        const int hq = q >> 1;
        #pragma unroll
        for (int n = 0; n < 4; n++) {
            float p = sP[warp][n][hq];
            int dst = dsts[n];
            if (lane < 16) {
                float4 v = *reinterpret_cast<const float4*>(
                    &sKQV[(e_loc0 + n) * KQV_STRIDE + 128 + j0]);
                redAddV4(&g_wV[(size_t)dst * 64 + j0], v.x * p, v.y * p, v.z * p, v.w * p);
            } else {
                float4 et = *reinterpret_cast<const float4*>(
                    &sEA[(e_loc0 + n) * EA_STRIDE + j0]);
                redAddV4(&g_rowV[(size_t)dst * 64 + j0], et.x * p, et.y * p, et.z * p, et.w * p);
            }
        }
        __syncwarp();
    }
}

// ---------------- kernel 4: finalize wV = (wV_raw + rowV_raw @ VeRow) / den ----
__global__ void k_final(const float* __restrict__ VeRow, float* __restrict__ wV_out) {
    int i = blockIdx.x * blockDim.x + threadIdx.x;
    if (i >= N_NODES * HDIM) return;
    int n = i >> 6, j = i & 63;
    int h = j >> 3, c = j & 7;
    float inv = 1.0f / (g_den[(size_t)n * 8 + h] + 1e-16f);
    float acc = g_wV[i];
    const float* rv = &g_rowV[(size_t)n * 64 + h * 8];
    #pragma unroll
    for (int d = 0; d < 8; d++)
        acc = fmaf(rv[d], __ldg(&VeRow[d * 64 + h * 8 + c]), acc);
    wV_out[i] = acc * inv;
}

// ---------------- launch ----------------
extern "C" void kernel_launch(void* const* d_in, const int* in_sizes, int n_in,
                              void* d_out, int out_size) {
    const float* x         = (const float*)d_in[0];
    const float* edge_attr = (const float*)d_in[1];
    const void*  ei_raw    = d_in[2];
    const float* Wq = (const float*)d_in[3];
    const float* bq = (const float*)d_in[4];
    const float* Wk = (const float*)d_in[5];
    const float* bk = (const float*)d_in[6];
    const float* We = (const float*)d_in[7];
    const float* be = (const float*)d_in[8];
    const float* Wv = (const float*)d_in[9];
    const float* bv = (const float*)d_in[10];
    const float* Aw = (const float*)d_in[11];
    const float* VeRow = (const float*)d_in[12];

    float* out    = (float*)d_out;
    float* wV_out = out;
    float* wE_out = out + (size_t)N_NODES * HDIM;

    cudaFuncSetAttribute(k_edge, cudaFuncAttributeMaxDynamicSharedMemorySize,
                         SMEM_EDGE_BYTES);

    k_init<<<(N_NODES * HDIM / 4 + 255) / 256, 256>>>();
    k_detect<<<(N_EDGES + 255) / 256, 256>>>((const unsigned*)ei_raw);
    k_nodeproj<<<(N_NODES + 31) / 32, 256>>>(x, Wq, bq, Wk, bk, Wv, bv);
    k_edge<<<EDGE_GRID, 256, SMEM_EDGE_BYTES>>>(edge_attr, ei_raw, We, be, Aw, wE_out);
    k_final<<<(N_NODES * HDIM + 255) / 256, 256>>>(VeRow, wV_out);
}